// round 7
// baseline (speedup 1.0000x reference)
#include <cuda_runtime.h>
#include <cuda_bf16.h>
#include <cuda_fp16.h>
#include <cstdint>

#define NNODES 100000
#define NEDGES 1600000

// ---------------- scratch (static __device__ — allocation-free) ----------------
__device__ int g_deg[NNODES], g_rowptr[NNODES], g_cursor[NNODES], g_col[NEDGES];
__device__ int g_bsum[512], g_boff[512];
// bf16 hi/lo planes (GEMM operands / outputs)
__device__ __nv_bfloat16 g_xh[NNODES * 64],   g_xl[NNODES * 64];
__device__ __nv_bfloat16 g_mh[NNODES * 128],  g_ml[NNODES * 128];
__device__ __nv_bfloat16 g_h1h[NNODES * 128], g_h1l[NNODES * 128];
__device__ __nv_bfloat16 g_h2h[NNODES * 128], g_h2l[NNODES * 128];
__device__ __nv_bfloat16 g_h3h[NNODES * 256], g_h3l[NNODES * 256];
__device__ __nv_bfloat16 g_wth[256 * 256],    g_wtl[256 * 256];
// fp16 shadows (agg gather path)
__device__ __half g_xf [NNODES * 64];
__device__ __half g_hf1[NNODES * 128];
__device__ __half g_hf2[NNODES * 128];

// ---------------- helpers ----------------
__device__ __forceinline__ uint32_t sw128(uint32_t b) { return b ^ ((b >> 3) & 0x70); }
__device__ __forceinline__ uint32_t cvta_smem(const void* p) {
    uint32_t a;
    asm("{ .reg .u64 t; cvta.to.shared.u64 t, %1; cvt.u32.u64 %0, t; }" : "=r"(a) : "l"(p));
    return a;
}
__device__ __forceinline__ void cpa16(uint32_t dst, const void* src, int sz) {
    asm volatile("cp.async.cg.shared.global [%0], [%1], 16, %2;"
                 :: "r"(dst), "l"(src), "r"(sz) : "memory");
}
__device__ __forceinline__ void ldsm4(uint32_t& r0, uint32_t& r1, uint32_t& r2, uint32_t& r3,
                                      uint32_t addr) {
    asm volatile("ldmatrix.sync.aligned.m8n8.x4.shared.b16 {%0,%1,%2,%3}, [%4];"
                 : "=r"(r0), "=r"(r1), "=r"(r2), "=r"(r3) : "r"(addr));
}
__device__ __forceinline__ void mma16816(float* c, const uint32_t* a, uint32_t b0, uint32_t b1) {
    asm volatile(
        "mma.sync.aligned.m16n8k16.row.col.f32.bf16.bf16.f32 "
        "{%0,%1,%2,%3}, {%4,%5,%6,%7}, {%8,%9}, {%0,%1,%2,%3};"
        : "+f"(c[0]), "+f"(c[1]), "+f"(c[2]), "+f"(c[3])
        : "r"(a[0]), "r"(a[1]), "r"(a[2]), "r"(a[3]), "r"(b0), "r"(b1));
}
__device__ __forceinline__ void split2(float v, __nv_bfloat16& h, __nv_bfloat16& l) {
    h = __float2bfloat16(v);
    l = __float2bfloat16(v - __bfloat162float(h));
}
__device__ __forceinline__ void split4(float4 v, uint2& H, uint2& L) {
    __nv_bfloat16 h0, l0, h1, l1, h2, l2, h3, l3;
    split2(v.x, h0, l0); split2(v.y, h1, l1);
    split2(v.z, h2, l2); split2(v.w, h3, l3);
    __nv_bfloat162 ph0 = __halves2bfloat162(h0, h1), ph1 = __halves2bfloat162(h2, h3);
    __nv_bfloat162 pl0 = __halves2bfloat162(l0, l1), pl1 = __halves2bfloat162(l2, l3);
    H = make_uint2(*(uint32_t*)&ph0, *(uint32_t*)&ph1);
    L = make_uint2(*(uint32_t*)&pl0, *(uint32_t*)&pl1);
}

// ---------------- CSR build ----------------
__global__ void k_zero_deg(int n) {
    int i = blockIdx.x * blockDim.x + threadIdx.x;
    if (i < n) g_deg[i] = 0;
}
__global__ void k_count(const int* __restrict__ dst, int E) {
    int e = blockIdx.x * blockDim.x + threadIdx.x;
    if (e < E) atomicAdd(&g_deg[dst[e]], 1);
}
__global__ void k_scan1(int n) {
    int tid = threadIdx.x, lane = tid & 31, warp = tid >> 5;
    int i = blockIdx.x * 256 + tid;
    int v = (i < n) ? g_deg[i] : 0;
    int x = v;
    #pragma unroll
    for (int o = 1; o < 32; o <<= 1) {
        int t = __shfl_up_sync(0xffffffffu, x, o);
        if (lane >= o) x += t;
    }
    __shared__ int wq[8];
    if (lane == 31) wq[warp] = x;
    __syncthreads();
    if (warp == 0) {
        int y = (lane < 8) ? wq[lane] : 0;
        int z = y;
        #pragma unroll
        for (int o = 1; o < 8; o <<= 1) {
            int t = __shfl_up_sync(0xffffffffu, z, o);
            if (lane >= o) z += t;
        }
        if (lane < 8) wq[lane] = z - y;
        if (lane == 7) g_bsum[blockIdx.x] = z;
    }
    __syncthreads();
    if (i < n) g_rowptr[i] = wq[warp] + x - v;
}
__global__ void k_scan2(int nb) {
    int tid = threadIdx.x, lane = tid & 31, warp = tid >> 5;
    int v = (tid < nb) ? g_bsum[tid] : 0;
    int x = v;
    #pragma unroll
    for (int o = 1; o < 32; o <<= 1) {
        int t = __shfl_up_sync(0xffffffffu, x, o);
        if (lane >= o) x += t;
    }
    __shared__ int wq[16];
    if (lane == 31) wq[warp] = x;
    __syncthreads();
    if (warp == 0) {
        int y = (lane < 16) ? wq[lane] : 0;
        int z = y;
        #pragma unroll
        for (int o = 1; o < 16; o <<= 1) {
            int t = __shfl_up_sync(0xffffffffu, z, o);
            if (lane >= o) z += t;
        }
        if (lane < 16) wq[lane] = z - y;
    }
    __syncthreads();
    if (tid < nb) g_boff[tid] = wq[warp] + x - v;
}
__global__ void k_scan3(int n) {
    int i = blockIdx.x * blockDim.x + threadIdx.x;
    if (i < n) {
        int r = g_rowptr[i] + g_boff[i >> 8];
        g_rowptr[i] = r;
        g_cursor[i] = r;
    }
}
__global__ void k_fill(const int* __restrict__ src, const int* __restrict__ dst, int E) {
    int e = blockIdx.x * blockDim.x + threadIdx.x;
    if (e < E) {
        int p = atomicAdd(&g_cursor[dst[e]], 1);
        g_col[p] = src[e];
    }
}

// ---------------- x -> fp16 shadow + bf16 planes ----------------
__global__ void k_cvt_x(const float* __restrict__ x, int n4) {
    int i = blockIdx.x * blockDim.x + threadIdx.x;
    if (i < n4) {
        float4 v = *(const float4*)(x + i * 4);
        uint2 H, L; split4(v, H, L);
        *(uint2*)(g_xh + i * 4) = H;
        *(uint2*)(g_xl + i * 4) = L;
        __half2 f0 = __floats2half2_rn(v.x, v.y), f1 = __floats2half2_rn(v.z, v.w);
        *(__half2*)(g_xf + i * 4)     = f0;
        *(__half2*)(g_xf + i * 4 + 2) = f1;
    }
}

// ---------------- weight prep: planes of Wt[n][k] = (k<K1 ? Wl[k][n] : Wr[k-K1][n]) ----------------
__global__ void k_prep_w(const float* __restrict__ Wl, const float* __restrict__ Wr,
                         int K1, int KT, int N) {
    int i = blockIdx.x * blockDim.x + threadIdx.x;
    if (i >= N * KT) return;
    int n = i / KT, k = i % KT;
    float v = (k < K1) ? Wl[k * N + n] : Wr[(k - K1) * N + n];
    __nv_bfloat16 h, l; split2(v, h, l);
    g_wth[n * KT + k] = h;
    g_wtl[n * KT + k] = l;
}

// ---------------- mean aggregation (fp16 gather, fp32 accum, bf16-plane output) ----------------
// D=64: lane owns 2 elems
__global__ void k_agg1h(const __half* __restrict__ xf, int n) {
    int gt = blockIdx.x * blockDim.x + threadIdx.x;
    int node = gt >> 5, lane = gt & 31;
    if (node >= n) return;
    float a0 = 0.f, a1 = 0.f;
    int s = g_rowptr[node], d = g_deg[node];
    int e = s, end = s + d;
    for (; e + 1 < end; e += 2) {
        float2 p0 = __half22float2(*(const __half2*)(xf + (size_t)g_col[e]     * 64 + 2 * lane));
        float2 p1 = __half22float2(*(const __half2*)(xf + (size_t)g_col[e + 1] * 64 + 2 * lane));
        a0 += p0.x + p1.x; a1 += p0.y + p1.y;
    }
    if (e < end) {
        float2 p0 = __half22float2(*(const __half2*)(xf + (size_t)g_col[e] * 64 + 2 * lane));
        a0 += p0.x; a1 += p0.y;
    }
    float inv = 1.0f / (float)(d > 0 ? d : 1);
    a0 *= inv; a1 *= inv;
    __nv_bfloat16 h0, l0, h1, l1;
    split2(a0, h0, l0); split2(a1, h1, l1);
    __nv_bfloat162 ph = __halves2bfloat162(h0, h1), pl = __halves2bfloat162(l0, l1);
    size_t o = (size_t)node * 64 + 2 * lane;
    *(uint32_t*)(g_mh + o) = *(uint32_t*)&ph;
    *(uint32_t*)(g_ml + o) = *(uint32_t*)&pl;
}
// D=128: lane owns 4 elems
__global__ void k_agg2h(const __half* __restrict__ hf, int n) {
    int gt = blockIdx.x * blockDim.x + threadIdx.x;
    int node = gt >> 5, lane = gt & 31;
    if (node >= n) return;
    float a0 = 0.f, a1 = 0.f, a2 = 0.f, a3 = 0.f;
    int s = g_rowptr[node], d = g_deg[node];
    int e = s, end = s + d;
    for (; e + 1 < end; e += 2) {
        uint2 u0 = *(const uint2*)(hf + (size_t)g_col[e]     * 128 + 4 * lane);
        uint2 u1 = *(const uint2*)(hf + (size_t)g_col[e + 1] * 128 + 4 * lane);
        float2 f0 = __half22float2(*(__half2*)&u0.x), f1 = __half22float2(*(__half2*)&u0.y);
        float2 f2 = __half22float2(*(__half2*)&u1.x), f3 = __half22float2(*(__half2*)&u1.y);
        a0 += f0.x + f2.x; a1 += f0.y + f2.y;
        a2 += f1.x + f3.x; a3 += f1.y + f3.y;
    }
    if (e < end) {
        uint2 u0 = *(const uint2*)(hf + (size_t)g_col[e] * 128 + 4 * lane);
        float2 f0 = __half22float2(*(__half2*)&u0.x), f1 = __half22float2(*(__half2*)&u0.y);
        a0 += f0.x; a1 += f0.y; a2 += f1.x; a3 += f1.y;
    }
    float inv = 1.0f / (float)(d > 0 ? d : 1);
    uint2 H, L;
    split4(make_float4(a0 * inv, a1 * inv, a2 * inv, a3 * inv), H, L);
    size_t o = (size_t)node * 128 + 4 * lane;
    *(uint2*)(g_mh + o) = H;
    *(uint2*)(g_ml + o) = L;
}

// ---------------- cp.async 2-stage HMMA GEMM (BK=64, 128KB smem, 1 CTA/SM) ----------------
// out planes = relu([A1|A2] @ Wt^T + bias); optional fp16 shadow for next agg.
// Stage layout (64KB): AH 0, AL 16K, WH 32K, WL 48K. Tiles 128 rows x 128B, sw128.
#define ST_SZ   65536
#define SM_TOT  131072

template <int K1, int K2, int NT>
__global__ void __launch_bounds__(256, 1) k_gemm_cp(
    const __nv_bfloat16* __restrict__ A1h, const __nv_bfloat16* __restrict__ A1l,
    const __nv_bfloat16* __restrict__ A2h, const __nv_bfloat16* __restrict__ A2l,
    const float* __restrict__ bias,
    __nv_bfloat16* __restrict__ Oh, __nv_bfloat16* __restrict__ Ol,
    __half* __restrict__ Of, int M)
{
    extern __shared__ char smem[];
    constexpr int KT = K1 + K2;
    constexpr int NC = KT / 64;
    uint32_t sb = cvta_smem(smem);
    int tid = threadIdx.x, lane = tid & 31, wid = tid >> 5;
    int wm = wid & 1, wn = wid >> 1;                       // 2m x 4n warp grid
    int bm = blockIdx.y * 128, bn = blockIdx.x * 128;

    float acc[4][4][4];
    #pragma unroll
    for (int mt = 0; mt < 4; mt++)
        #pragma unroll
        for (int nt = 0; nt < 4; nt++)
            #pragma unroll
            for (int j = 0; j < 4; j++) acc[mt][nt][j] = 0.f;

    // ldmatrix per-lane components (identical to R4/R6)
    int ar = lane & 15, ak = (lane >> 4) * 16;
    int nr = (lane & 7) + ((lane >> 4) << 3);
    int nk = ((lane >> 3) & 1) * 16;

    // this thread fills 4 chunks/plane: row = id>>3, cc = id&7
    int frow = tid >> 3, fcc = tid & 7;

    auto load_stage = [&](int st, int c) {
        const __nv_bfloat16 *Ah, *Al; int Ks, kb;
        if (c * 64 < K1) { Ah = A1h; Al = A1l; Ks = K1; kb = c * 64; }
        else             { Ah = A2h; Al = A2l; Ks = K2; kb = c * 64 - K1; }
        uint32_t base = sb + st * ST_SZ;
        #pragma unroll
        for (int q = 0; q < 4; q++) {
            int row = frow + q * 32;
            uint32_t so = base + sw128((uint32_t)(row * 128 + fcc * 16));
            int gr = bm + row;
            int sz = (gr < M) ? 16 : 0;
            int grc = (gr < M) ? gr : 0;
            const __nv_bfloat16* a_src = Ah + (size_t)grc * Ks + kb + fcc * 8;
            const __nv_bfloat16* l_src = Al + (size_t)grc * Ks + kb + fcc * 8;
            size_t wo = (size_t)(bn + row) * KT + c * 64 + fcc * 8;
            cpa16(so,         a_src, sz);
            cpa16(so + 16384, l_src, sz);
            cpa16(so + 32768, g_wth + wo, 16);
            cpa16(so + 49152, g_wtl + wo, 16);
        }
        asm volatile("cp.async.commit_group;" ::: "memory");
    };

    auto compute_stage = [&](int st) {
        uint32_t base = sb + st * ST_SZ;
        #pragma unroll
        for (int kk = 0; kk < 4; kk++) {
            uint32_t A_[4][4], W1[4][2], W2[4][2];
            uint32_t aoff[4], woff[2];
            #pragma unroll
            for (int mt = 0; mt < 4; mt++) {
                aoff[mt] = sw128((uint32_t)((wm * 64 + mt * 16 + ar) * 128 + ak + kk * 32));
                ldsm4(A_[mt][0], A_[mt][1], A_[mt][2], A_[mt][3], base + aoff[mt]);
            }
            #pragma unroll
            for (int h2 = 0; h2 < 2; h2++) {
                woff[h2] = sw128((uint32_t)((wn * 32 + h2 * 16 + nr) * 128 + nk + kk * 32));
                ldsm4(W1[h2 * 2][0], W1[h2 * 2][1], W1[h2 * 2 + 1][0], W1[h2 * 2 + 1][1],
                      base + 32768 + woff[h2]);
            }
            // hi(A) x hi(W)
            #pragma unroll
            for (int mt = 0; mt < 4; mt++)
                #pragma unroll
                for (int nt = 0; nt < 4; nt++)
                    mma16816(acc[mt][nt], A_[mt], W1[nt][0], W1[nt][1]);
            // hi(A) x lo(W)
            #pragma unroll
            for (int h2 = 0; h2 < 2; h2++)
                ldsm4(W2[h2 * 2][0], W2[h2 * 2][1], W2[h2 * 2 + 1][0], W2[h2 * 2 + 1][1],
                      base + 49152 + woff[h2]);
            #pragma unroll
            for (int mt = 0; mt < 4; mt++)
                #pragma unroll
                for (int nt = 0; nt < 4; nt++)
                    mma16816(acc[mt][nt], A_[mt], W2[nt][0], W2[nt][1]);
            // lo(A) x hi(W) — reuse A_ regs
            #pragma unroll
            for (int mt = 0; mt < 4; mt++)
                ldsm4(A_[mt][0], A_[mt][1], A_[mt][2], A_[mt][3], base + 16384 + aoff[mt]);
            #pragma unroll
            for (int mt = 0; mt < 4; mt++)
                #pragma unroll
                for (int nt = 0; nt < 4; nt++)
                    mma16816(acc[mt][nt], A_[mt], W1[nt][0], W1[nt][1]);
        }
    };

    load_stage(0, 0);
    for (int c = 0; c < NC; c++) {
        if (c + 1 < NC) {
            load_stage((c + 1) & 1, c + 1);
            asm volatile("cp.async.wait_group 1;" ::: "memory");
        } else {
            asm volatile("cp.async.wait_group 0;" ::: "memory");
        }
        __syncthreads();
        compute_stage(c & 1);
        __syncthreads();
    }

    // epilogue: bias + relu -> bf16 planes (+ fp16 shadow)
    int g = lane >> 2, t = lane & 3;
    #pragma unroll
    for (int nt = 0; nt < 4; nt++) {
        int col = bn + wn * 32 + nt * 8 + 2 * t;
        float2 bv = *(const float2*)(bias + col);
        #pragma unroll
        for (int mt = 0; mt < 4; mt++) {
            int r0 = bm + wm * 64 + mt * 16 + g;
            int r1 = r0 + 8;
            #pragma unroll
            for (int half_ = 0; half_ < 2; half_++) {
                int r = half_ ? r1 : r0;
                if (r >= M) continue;
                float f0 = fmaxf(acc[mt][nt][half_ * 2]     + bv.x, 0.f);
                float f1 = fmaxf(acc[mt][nt][half_ * 2 + 1] + bv.y, 0.f);
                __nv_bfloat16 h0, l0, h1, l1;
                split2(f0, h0, l0); split2(f1, h1, l1);
                __nv_bfloat162 ph = __halves2bfloat162(h0, h1);
                __nv_bfloat162 pl = __halves2bfloat162(l0, l1);
                *(uint32_t*)(Oh + (size_t)r * NT + col) = *(uint32_t*)&ph;
                *(uint32_t*)(Ol + (size_t)r * NT + col) = *(uint32_t*)&pl;
                if (Of) *(__half2*)(Of + (size_t)r * NT + col) = __floats2half2_rn(f0, f1);
            }
        }
    }
}

// ---------------- final FC: out = (hi+lo) @ Wfc + bfc  (256 -> 9), warp per node ----------------
__global__ void k_fc(const __nv_bfloat16* __restrict__ hh, const __nv_bfloat16* __restrict__ hl,
                     const float* __restrict__ W, const float* __restrict__ b,
                     float* __restrict__ out, int n) {
    __shared__ float sW[256 * 9];
    __shared__ float sb[9];
    for (int i = threadIdx.x; i < 256 * 9; i += blockDim.x) sW[i] = W[i];
    if (threadIdx.x < 9) sb[threadIdx.x] = b[threadIdx.x];
    __syncthreads();
    int warp = threadIdx.x >> 5, lane = threadIdx.x & 31;
    int node = blockIdx.x * 8 + warp;
    if (node >= n) return;
    float hv[8];
    #pragma unroll
    for (int r = 0; r < 8; r++) {
        size_t o = (size_t)node * 256 + r * 32 + lane;
        hv[r] = __bfloat162float(hh[o]) + __bfloat162float(hl[o]);
    }
    #pragma unroll
    for (int j = 0; j < 9; j++) {
        float s = 0.f;
        #pragma unroll
        for (int r = 0; r < 8; r++) s += hv[r] * sW[(r * 32 + lane) * 9 + j];
        #pragma unroll
        for (int o = 16; o > 0; o >>= 1) s += __shfl_xor_sync(0xffffffffu, s, o);
        if (lane == 0) out[node * 9 + j] = s + sb[j];
    }
}

// ---------------- launch ----------------
extern "C" void kernel_launch(void* const* d_in, const int* in_sizes, int n_in,
                              void* d_out, int out_size) {
    (void)n_in; (void)out_size;
    const float* x   = (const float*)d_in[0];
    const int*   ei  = (const int*)d_in[1];
    const float* Wl1 = (const float*)d_in[2];
    const float* bl1 = (const float*)d_in[3];
    const float* Wr1 = (const float*)d_in[4];
    const float* Wl2 = (const float*)d_in[5];
    const float* bl2 = (const float*)d_in[6];
    const float* Wr2 = (const float*)d_in[7];
    const float* Wl3 = (const float*)d_in[8];
    const float* bl3 = (const float*)d_in[9];
    const float* Wr3 = (const float*)d_in[10];
    const float* Wfc = (const float*)d_in[11];
    const float* bfc = (const float*)d_in[12];
    float* out = (float*)d_out;

    int M = in_sizes[0] / 64;
    int E = in_sizes[1] / 2;
    const int* src = ei;
    const int* dst = ei + E;

    __nv_bfloat16 *xh, *xl, *mh, *ml, *h1h, *h1l, *h2h, *h2l, *h3h, *h3l;
    __half *pxf, *phf1, *phf2;
    cudaGetSymbolAddress((void**)&xh,  g_xh);
    cudaGetSymbolAddress((void**)&xl,  g_xl);
    cudaGetSymbolAddress((void**)&mh,  g_mh);
    cudaGetSymbolAddress((void**)&ml,  g_ml);
    cudaGetSymbolAddress((void**)&h1h, g_h1h);
    cudaGetSymbolAddress((void**)&h1l, g_h1l);
    cudaGetSymbolAddress((void**)&h2h, g_h2h);
    cudaGetSymbolAddress((void**)&h2l, g_h2l);
    cudaGetSymbolAddress((void**)&h3h, g_h3h);
    cudaGetSymbolAddress((void**)&h3l, g_h3l);
    cudaGetSymbolAddress((void**)&pxf, g_xf);
    cudaGetSymbolAddress((void**)&phf1, g_hf1);
    cudaGetSymbolAddress((void**)&phf2, g_hf2);

    cudaFuncSetAttribute(k_gemm_cp<64, 64, 128>,
                         cudaFuncAttributeMaxDynamicSharedMemorySize, SM_TOT);
    cudaFuncSetAttribute(k_gemm_cp<128, 128, 128>,
                         cudaFuncAttributeMaxDynamicSharedMemorySize, SM_TOT);
    cudaFuncSetAttribute(k_gemm_cp<128, 128, 256>,
                         cudaFuncAttributeMaxDynamicSharedMemorySize, SM_TOT);

    int nbN = (M + 255) / 256;
    int nbE = (E + 255) / 256;
    int nbW = (M * 32 + 255) / 256;   // warp per node
    int gM  = (M + 127) / 128;        // 782

    // CSR build
    k_zero_deg<<<nbN, 256>>>(M);
    k_count<<<nbE, 256>>>(dst, E);
    k_scan1<<<nbN, 256>>>(M);
    k_scan2<<<1, 512>>>(nbN);
    k_scan3<<<nbN, 256>>>(M);
    k_fill<<<nbE, 256>>>(src, dst, E);

    // x -> planes + fp16 shadow
    k_cvt_x<<<(M * 16 + 255) / 256, 256>>>(x, M * 16);

    // ---- layer 1: 64 -> 128 ----
    k_prep_w<<<(128 * 128 + 255) / 256, 256>>>(Wl1, Wr1, 64, 128, 128);
    k_agg1h<<<nbW, 256>>>(pxf, M);
    k_gemm_cp<64, 64, 128><<<dim3(1, gM), 256, SM_TOT>>>(
        mh, ml, xh, xl, bl1, h1h, h1l, phf1, M);

    // ---- layer 2: 128 -> 128 ----
    k_prep_w<<<(128 * 256 + 255) / 256, 256>>>(Wl2, Wr2, 128, 256, 128);
    k_agg2h<<<nbW, 256>>>(phf1, M);
    k_gemm_cp<128, 128, 128><<<dim3(1, gM), 256, SM_TOT>>>(
        mh, ml, h1h, h1l, bl2, h2h, h2l, phf2, M);

    // ---- layer 3: 128 -> 256 ----
    k_prep_w<<<(256 * 256 + 255) / 256, 256>>>(Wl3, Wr3, 128, 256, 256);
    k_agg2h<<<nbW, 256>>>(phf2, M);
    k_gemm_cp<128, 128, 256><<<dim3(2, gM), 256, SM_TOT>>>(
        mh, ml, h2h, h2l, bl3, h3h, h3l, (__half*)nullptr, M);

    // ---- FC head: 256 -> 9 ----
    k_fc<<<(M + 7) / 8, 256>>>(h3h, h3l, Wfc, bfc, out, M);
}

// round 8
// speedup vs baseline: 1.0098x; 1.0098x over previous
#include <cuda_runtime.h>
#include <cuda_bf16.h>
#include <cuda_fp16.h>
#include <cstdint>

#define NNODES 100000
#define NEDGES 1600000

// ---------------- scratch (static __device__ — allocation-free) ----------------
__device__ int g_deg[NNODES], g_rowptr[NNODES], g_cursor[NNODES], g_col[NEDGES];
__device__ int g_bsum[512], g_boff[512];
// bf16 hi/lo planes (GEMM operands / outputs)
__device__ __nv_bfloat16 g_xh[NNODES * 64],   g_xl[NNODES * 64];
__device__ __nv_bfloat16 g_mh[NNODES * 128],  g_ml[NNODES * 128];
__device__ __nv_bfloat16 g_h1h[NNODES * 128], g_h1l[NNODES * 128];
__device__ __nv_bfloat16 g_h2h[NNODES * 128], g_h2l[NNODES * 128];
__device__ __nv_bfloat16 g_h3h[NNODES * 256], g_h3l[NNODES * 256];
__device__ __nv_bfloat16 g_wth[256 * 256],    g_wtl[256 * 256];
// fp16 shadows (agg gather path)
__device__ __half g_xf [NNODES * 64];
__device__ __half g_hf1[NNODES * 128];
__device__ __half g_hf2[NNODES * 128];

// ---------------- helpers ----------------
__device__ __forceinline__ uint32_t sw128(uint32_t b) { return b ^ ((b >> 3) & 0x70); }
__device__ __forceinline__ uint32_t cvta_smem(const void* p) {
    uint32_t a;
    asm("{ .reg .u64 t; cvta.to.shared.u64 t, %1; cvt.u32.u64 %0, t; }" : "=r"(a) : "l"(p));
    return a;
}
__device__ __forceinline__ void cpa16(uint32_t dst, const void* src, int sz) {
    asm volatile("cp.async.cg.shared.global [%0], [%1], 16, %2;"
                 :: "r"(dst), "l"(src), "r"(sz) : "memory");
}
__device__ __forceinline__ void ldsm4(uint32_t& r0, uint32_t& r1, uint32_t& r2, uint32_t& r3,
                                      uint32_t addr) {
    asm volatile("ldmatrix.sync.aligned.m8n8.x4.shared.b16 {%0,%1,%2,%3}, [%4];"
                 : "=r"(r0), "=r"(r1), "=r"(r2), "=r"(r3) : "r"(addr));
}
__device__ __forceinline__ void mma16816(float* c, const uint32_t* a, uint32_t b0, uint32_t b1) {
    asm volatile(
        "mma.sync.aligned.m16n8k16.row.col.f32.bf16.bf16.f32 "
        "{%0,%1,%2,%3}, {%4,%5,%6,%7}, {%8,%9}, {%0,%1,%2,%3};"
        : "+f"(c[0]), "+f"(c[1]), "+f"(c[2]), "+f"(c[3])
        : "r"(a[0]), "r"(a[1]), "r"(a[2]), "r"(a[3]), "r"(b0), "r"(b1));
}
__device__ __forceinline__ void split2(float v, __nv_bfloat16& h, __nv_bfloat16& l) {
    h = __float2bfloat16(v);
    l = __float2bfloat16(v - __bfloat162float(h));
}
__device__ __forceinline__ void split4(float4 v, uint2& H, uint2& L) {
    __nv_bfloat16 h0, l0, h1, l1, h2, l2, h3, l3;
    split2(v.x, h0, l0); split2(v.y, h1, l1);
    split2(v.z, h2, l2); split2(v.w, h3, l3);
    __nv_bfloat162 ph0 = __halves2bfloat162(h0, h1), ph1 = __halves2bfloat162(h2, h3);
    __nv_bfloat162 pl0 = __halves2bfloat162(l0, l1), pl1 = __halves2bfloat162(l2, l3);
    H = make_uint2(*(uint32_t*)&ph0, *(uint32_t*)&ph1);
    L = make_uint2(*(uint32_t*)&pl0, *(uint32_t*)&pl1);
}

// ---------------- CSR build ----------------
__global__ void k_zero_deg(int n) {
    int i = blockIdx.x * blockDim.x + threadIdx.x;
    if (i < n) g_deg[i] = 0;
}
__global__ void k_count(const int* __restrict__ dst, int E) {
    int e = blockIdx.x * blockDim.x + threadIdx.x;
    if (e < E) atomicAdd(&g_deg[dst[e]], 1);
}
__global__ void k_scan1(int n) {
    int tid = threadIdx.x, lane = tid & 31, warp = tid >> 5;
    int i = blockIdx.x * 256 + tid;
    int v = (i < n) ? g_deg[i] : 0;
    int x = v;
    #pragma unroll
    for (int o = 1; o < 32; o <<= 1) {
        int t = __shfl_up_sync(0xffffffffu, x, o);
        if (lane >= o) x += t;
    }
    __shared__ int wq[8];
    if (lane == 31) wq[warp] = x;
    __syncthreads();
    if (warp == 0) {
        int y = (lane < 8) ? wq[lane] : 0;
        int z = y;
        #pragma unroll
        for (int o = 1; o < 8; o <<= 1) {
            int t = __shfl_up_sync(0xffffffffu, z, o);
            if (lane >= o) z += t;
        }
        if (lane < 8) wq[lane] = z - y;
        if (lane == 7) g_bsum[blockIdx.x] = z;
    }
    __syncthreads();
    if (i < n) g_rowptr[i] = wq[warp] + x - v;
}
__global__ void k_scan2(int nb) {
    int tid = threadIdx.x, lane = tid & 31, warp = tid >> 5;
    int v = (tid < nb) ? g_bsum[tid] : 0;
    int x = v;
    #pragma unroll
    for (int o = 1; o < 32; o <<= 1) {
        int t = __shfl_up_sync(0xffffffffu, x, o);
        if (lane >= o) x += t;
    }
    __shared__ int wq[16];
    if (lane == 31) wq[warp] = x;
    __syncthreads();
    if (warp == 0) {
        int y = (lane < 16) ? wq[lane] : 0;
        int z = y;
        #pragma unroll
        for (int o = 1; o < 16; o <<= 1) {
            int t = __shfl_up_sync(0xffffffffu, z, o);
            if (lane >= o) z += t;
        }
        if (lane < 16) wq[lane] = z - y;
    }
    __syncthreads();
    if (tid < nb) g_boff[tid] = wq[warp] + x - v;
}
__global__ void k_scan3(int n) {
    int i = blockIdx.x * blockDim.x + threadIdx.x;
    if (i < n) {
        int r = g_rowptr[i] + g_boff[i >> 8];
        g_rowptr[i] = r;
        g_cursor[i] = r;
    }
}
__global__ void k_fill(const int* __restrict__ src, const int* __restrict__ dst, int E) {
    int e = blockIdx.x * blockDim.x + threadIdx.x;
    if (e < E) {
        int p = atomicAdd(&g_cursor[dst[e]], 1);
        g_col[p] = src[e];
    }
}

// ---------------- x -> fp16 shadow + bf16 planes ----------------
__global__ void k_cvt_x(const float* __restrict__ x, int n4) {
    int i = blockIdx.x * blockDim.x + threadIdx.x;
    if (i < n4) {
        float4 v = *(const float4*)(x + i * 4);
        uint2 H, L; split4(v, H, L);
        *(uint2*)(g_xh + i * 4) = H;
        *(uint2*)(g_xl + i * 4) = L;
        __half2 f0 = __floats2half2_rn(v.x, v.y), f1 = __floats2half2_rn(v.z, v.w);
        *(__half2*)(g_xf + i * 4)     = f0;
        *(__half2*)(g_xf + i * 4 + 2) = f1;
    }
}

// ---------------- weight prep: planes of Wt[n][k] = (k<K1 ? Wl[k][n] : Wr[k-K1][n]) ----------------
__global__ void k_prep_w(const float* __restrict__ Wl, const float* __restrict__ Wr,
                         int K1, int KT, int N) {
    int i = blockIdx.x * blockDim.x + threadIdx.x;
    if (i >= N * KT) return;
    int n = i / KT, k = i % KT;
    float v = (k < K1) ? Wl[k * N + n] : Wr[(k - K1) * N + n];
    __nv_bfloat16 h, l; split2(v, h, l);
    g_wth[n * KT + k] = h;
    g_wtl[n * KT + k] = l;
}

// ---------------- mean aggregation (fp16 gather, fp32 accum, bf16-plane output) ----------------
// D=64: lane owns 2 elems
__global__ void k_agg1h(const __half* __restrict__ xf, int n) {
    int gt = blockIdx.x * blockDim.x + threadIdx.x;
    int node = gt >> 5, lane = gt & 31;
    if (node >= n) return;
    float a0 = 0.f, a1 = 0.f;
    int s = g_rowptr[node], d = g_deg[node];
    int e = s, end = s + d;
    for (; e + 1 < end; e += 2) {
        float2 p0 = __half22float2(*(const __half2*)(xf + (size_t)g_col[e]     * 64 + 2 * lane));
        float2 p1 = __half22float2(*(const __half2*)(xf + (size_t)g_col[e + 1] * 64 + 2 * lane));
        a0 += p0.x + p1.x; a1 += p0.y + p1.y;
    }
    if (e < end) {
        float2 p0 = __half22float2(*(const __half2*)(xf + (size_t)g_col[e] * 64 + 2 * lane));
        a0 += p0.x; a1 += p0.y;
    }
    float inv = 1.0f / (float)(d > 0 ? d : 1);
    a0 *= inv; a1 *= inv;
    __nv_bfloat16 h0, l0, h1, l1;
    split2(a0, h0, l0); split2(a1, h1, l1);
    __nv_bfloat162 ph = __halves2bfloat162(h0, h1), pl = __halves2bfloat162(l0, l1);
    size_t o = (size_t)node * 64 + 2 * lane;
    *(uint32_t*)(g_mh + o) = *(uint32_t*)&ph;
    *(uint32_t*)(g_ml + o) = *(uint32_t*)&pl;
}
// D=128: lane owns 4 elems
__global__ void k_agg2h(const __half* __restrict__ hf, int n) {
    int gt = blockIdx.x * blockDim.x + threadIdx.x;
    int node = gt >> 5, lane = gt & 31;
    if (node >= n) return;
    float a0 = 0.f, a1 = 0.f, a2 = 0.f, a3 = 0.f;
    int s = g_rowptr[node], d = g_deg[node];
    int e = s, end = s + d;
    for (; e + 1 < end; e += 2) {
        uint2 u0 = *(const uint2*)(hf + (size_t)g_col[e]     * 128 + 4 * lane);
        uint2 u1 = *(const uint2*)(hf + (size_t)g_col[e + 1] * 128 + 4 * lane);
        float2 f0 = __half22float2(*(__half2*)&u0.x), f1 = __half22float2(*(__half2*)&u0.y);
        float2 f2 = __half22float2(*(__half2*)&u1.x), f3 = __half22float2(*(__half2*)&u1.y);
        a0 += f0.x + f2.x; a1 += f0.y + f2.y;
        a2 += f1.x + f3.x; a3 += f1.y + f3.y;
    }
    if (e < end) {
        uint2 u0 = *(const uint2*)(hf + (size_t)g_col[e] * 128 + 4 * lane);
        float2 f0 = __half22float2(*(__half2*)&u0.x), f1 = __half22float2(*(__half2*)&u0.y);
        a0 += f0.x; a1 += f0.y; a2 += f1.x; a3 += f1.y;
    }
    float inv = 1.0f / (float)(d > 0 ? d : 1);
    uint2 H, L;
    split4(make_float4(a0 * inv, a1 * inv, a2 * inv, a3 * inv), H, L);
    size_t o = (size_t)node * 128 + 4 * lane;
    *(uint2*)(g_mh + o) = H;
    *(uint2*)(g_ml + o) = L;
}

// ---------------- cp.async 2-stage HMMA GEMM (BK=64, 128KB smem, 1 CTA/SM) ----------------
// out planes = relu([A1|A2] @ Wt^T + bias); optional fp16 shadow for next agg.
// Stage layout (64KB): AH 0, AL 16K, WH 32K, WL 48K. Tiles 128 rows x 128B, sw128.
#define ST_SZ   65536
#define SM_TOT  131072

template <int K1, int K2, int NT>
__global__ void __launch_bounds__(256, 1) k_gemm_cp(
    const __nv_bfloat16* __restrict__ A1h, const __nv_bfloat16* __restrict__ A1l,
    const __nv_bfloat16* __restrict__ A2h, const __nv_bfloat16* __restrict__ A2l,
    const float* __restrict__ bias,
    __nv_bfloat16* __restrict__ Oh, __nv_bfloat16* __restrict__ Ol,
    __half* __restrict__ Of, int M)
{
    extern __shared__ char smem[];
    constexpr int KT = K1 + K2;
    constexpr int NC = KT / 64;
    uint32_t sb = cvta_smem(smem);
    int tid = threadIdx.x, lane = tid & 31, wid = tid >> 5;
    int wm = wid & 1, wn = wid >> 1;                       // 2m x 4n warp grid
    int bm = blockIdx.y * 128, bn = blockIdx.x * 128;

    float acc[4][4][4];
    #pragma unroll
    for (int mt = 0; mt < 4; mt++)
        #pragma unroll
        for (int nt = 0; nt < 4; nt++)
            #pragma unroll
            for (int j = 0; j < 4; j++) acc[mt][nt][j] = 0.f;

    // ldmatrix per-lane components (identical to R4/R6)
    int ar = lane & 15, ak = (lane >> 4) * 16;
    int nr = (lane & 7) + ((lane >> 4) << 3);
    int nk = ((lane >> 3) & 1) * 16;

    // this thread fills 4 chunks/plane: row = id>>3, cc = id&7
    int frow = tid >> 3, fcc = tid & 7;

    auto load_stage = [&](int st, int c) {
        const __nv_bfloat16 *Ah, *Al; int Ks, kb;
        if (c * 64 < K1) { Ah = A1h; Al = A1l; Ks = K1; kb = c * 64; }
        else             { Ah = A2h; Al = A2l; Ks = K2; kb = c * 64 - K1; }
        uint32_t base = sb + st * ST_SZ;
        #pragma unroll
        for (int q = 0; q < 4; q++) {
            int row = frow + q * 32;
            uint32_t so = base + sw128((uint32_t)(row * 128 + fcc * 16));
            int gr = bm + row;
            int sz = (gr < M) ? 16 : 0;
            int grc = (gr < M) ? gr : 0;
            const __nv_bfloat16* a_src = Ah + (size_t)grc * Ks + kb + fcc * 8;
            const __nv_bfloat16* l_src = Al + (size_t)grc * Ks + kb + fcc * 8;
            size_t wo = (size_t)(bn + row) * KT + c * 64 + fcc * 8;
            cpa16(so,         a_src, sz);
            cpa16(so + 16384, l_src, sz);
            cpa16(so + 32768, g_wth + wo, 16);
            cpa16(so + 49152, g_wtl + wo, 16);
        }
        asm volatile("cp.async.commit_group;" ::: "memory");
    };

    auto compute_stage = [&](int st) {
        uint32_t base = sb + st * ST_SZ;
        #pragma unroll
        for (int kk = 0; kk < 4; kk++) {
            uint32_t A_[4][4], W1[4][2], W2[4][2];
            uint32_t aoff[4], woff[2];
            #pragma unroll
            for (int mt = 0; mt < 4; mt++) {
                aoff[mt] = sw128((uint32_t)((wm * 64 + mt * 16 + ar) * 128 + ak + kk * 32));
                ldsm4(A_[mt][0], A_[mt][1], A_[mt][2], A_[mt][3], base + aoff[mt]);
            }
            #pragma unroll
            for (int h2 = 0; h2 < 2; h2++) {
                woff[h2] = sw128((uint32_t)((wn * 32 + h2 * 16 + nr) * 128 + nk + kk * 32));
                ldsm4(W1[h2 * 2][0], W1[h2 * 2][1], W1[h2 * 2 + 1][0], W1[h2 * 2 + 1][1],
                      base + 32768 + woff[h2]);
            }
            // hi(A) x hi(W)
            #pragma unroll
            for (int mt = 0; mt < 4; mt++)
                #pragma unroll
                for (int nt = 0; nt < 4; nt++)
                    mma16816(acc[mt][nt], A_[mt], W1[nt][0], W1[nt][1]);
            // hi(A) x lo(W)
            #pragma unroll
            for (int h2 = 0; h2 < 2; h2++)
                ldsm4(W2[h2 * 2][0], W2[h2 * 2][1], W2[h2 * 2 + 1][0], W2[h2 * 2 + 1][1],
                      base + 49152 + woff[h2]);
            #pragma unroll
            for (int mt = 0; mt < 4; mt++)
                #pragma unroll
                for (int nt = 0; nt < 4; nt++)
                    mma16816(acc[mt][nt], A_[mt], W2[nt][0], W2[nt][1]);
            // lo(A) x hi(W) — reuse A_ regs
            #pragma unroll
            for (int mt = 0; mt < 4; mt++)
                ldsm4(A_[mt][0], A_[mt][1], A_[mt][2], A_[mt][3], base + 16384 + aoff[mt]);
            #pragma unroll
            for (int mt = 0; mt < 4; mt++)
                #pragma unroll
                for (int nt = 0; nt < 4; nt++)
                    mma16816(acc[mt][nt], A_[mt], W1[nt][0], W1[nt][1]);
        }
    };

    load_stage(0, 0);
    for (int c = 0; c < NC; c++) {
        if (c + 1 < NC) {
            load_stage((c + 1) & 1, c + 1);
            asm volatile("cp.async.wait_group 1;" ::: "memory");
        } else {
            asm volatile("cp.async.wait_group 0;" ::: "memory");
        }
        __syncthreads();
        compute_stage(c & 1);
        __syncthreads();
    }

    // epilogue: bias + relu -> bf16 planes (+ fp16 shadow)
    int g = lane >> 2, t = lane & 3;
    #pragma unroll
    for (int nt = 0; nt < 4; nt++) {
        int col = bn + wn * 32 + nt * 8 + 2 * t;
        float2 bv = *(const float2*)(bias + col);
        #pragma unroll
        for (int mt = 0; mt < 4; mt++) {
            int r0 = bm + wm * 64 + mt * 16 + g;
            int r1 = r0 + 8;
            #pragma unroll
            for (int half_ = 0; half_ < 2; half_++) {
                int r = half_ ? r1 : r0;
                if (r >= M) continue;
                float f0 = fmaxf(acc[mt][nt][half_ * 2]     + bv.x, 0.f);
                float f1 = fmaxf(acc[mt][nt][half_ * 2 + 1] + bv.y, 0.f);
                __nv_bfloat16 h0, l0, h1, l1;
                split2(f0, h0, l0); split2(f1, h1, l1);
                __nv_bfloat162 ph = __halves2bfloat162(h0, h1);
                __nv_bfloat162 pl = __halves2bfloat162(l0, l1);
                *(uint32_t*)(Oh + (size_t)r * NT + col) = *(uint32_t*)&ph;
                *(uint32_t*)(Ol + (size_t)r * NT + col) = *(uint32_t*)&pl;
                if (Of) *(__half2*)(Of + (size_t)r * NT + col) = __floats2half2_rn(f0, f1);
            }
        }
    }
}

// ---------------- final FC: out = (hi+lo) @ Wfc + bfc  (256 -> 9), warp per node ----------------
__global__ void k_fc(const __nv_bfloat16* __restrict__ hh, const __nv_bfloat16* __restrict__ hl,
                     const float* __restrict__ W, const float* __restrict__ b,
                     float* __restrict__ out, int n) {
    __shared__ float sW[256 * 9];
    __shared__ float sb[9];
    for (int i = threadIdx.x; i < 256 * 9; i += blockDim.x) sW[i] = W[i];
    if (threadIdx.x < 9) sb[threadIdx.x] = b[threadIdx.x];
    __syncthreads();
    int warp = threadIdx.x >> 5, lane = threadIdx.x & 31;
    int node = blockIdx.x * 8 + warp;
    if (node >= n) return;
    float hv[8];
    #pragma unroll
    for (int r = 0; r < 8; r++) {
        size_t o = (size_t)node * 256 + r * 32 + lane;
        hv[r] = __bfloat162float(hh[o]) + __bfloat162float(hl[o]);
    }
    #pragma unroll
    for (int j = 0; j < 9; j++) {
        float s = 0.f;
        #pragma unroll
        for (int r = 0; r < 8; r++) s += hv[r] * sW[(r * 32 + lane) * 9 + j];
        #pragma unroll
        for (int o = 16; o > 0; o >>= 1) s += __shfl_xor_sync(0xffffffffu, s, o);
        if (lane == 0) out[node * 9 + j] = s + sb[j];
    }
}

// ---------------- launch ----------------
extern "C" void kernel_launch(void* const* d_in, const int* in_sizes, int n_in,
                              void* d_out, int out_size) {
    (void)n_in; (void)out_size;
    const float* x   = (const float*)d_in[0];
    const int*   ei  = (const int*)d_in[1];
    const float* Wl1 = (const float*)d_in[2];
    const float* bl1 = (const float*)d_in[3];
    const float* Wr1 = (const float*)d_in[4];
    const float* Wl2 = (const float*)d_in[5];
    const float* bl2 = (const float*)d_in[6];
    const float* Wr2 = (const float*)d_in[7];
    const float* Wl3 = (const float*)d_in[8];
    const float* bl3 = (const float*)d_in[9];
    const float* Wr3 = (const float*)d_in[10];
    const float* Wfc = (const float*)d_in[11];
    const float* bfc = (const float*)d_in[12];
    float* out = (float*)d_out;

    int M = in_sizes[0] / 64;
    int E = in_sizes[1] / 2;
    const int* src = ei;
    const int* dst = ei + E;

    __nv_bfloat16 *xh, *xl, *mh, *ml, *h1h, *h1l, *h2h, *h2l, *h3h, *h3l;
    __half *pxf, *phf1, *phf2;
    cudaGetSymbolAddress((void**)&xh,  g_xh);
    cudaGetSymbolAddress((void**)&xl,  g_xl);
    cudaGetSymbolAddress((void**)&mh,  g_mh);
    cudaGetSymbolAddress((void**)&ml,  g_ml);
    cudaGetSymbolAddress((void**)&h1h, g_h1h);
    cudaGetSymbolAddress((void**)&h1l, g_h1l);
    cudaGetSymbolAddress((void**)&h2h, g_h2h);
    cudaGetSymbolAddress((void**)&h2l, g_h2l);
    cudaGetSymbolAddress((void**)&h3h, g_h3h);
    cudaGetSymbolAddress((void**)&h3l, g_h3l);
    cudaGetSymbolAddress((void**)&pxf, g_xf);
    cudaGetSymbolAddress((void**)&phf1, g_hf1);
    cudaGetSymbolAddress((void**)&phf2, g_hf2);

    cudaFuncSetAttribute(k_gemm_cp<64, 64, 128>,
                         cudaFuncAttributeMaxDynamicSharedMemorySize, SM_TOT);
    cudaFuncSetAttribute(k_gemm_cp<128, 128, 128>,
                         cudaFuncAttributeMaxDynamicSharedMemorySize, SM_TOT);
    cudaFuncSetAttribute(k_gemm_cp<128, 128, 256>,
                         cudaFuncAttributeMaxDynamicSharedMemorySize, SM_TOT);

    int nbN = (M + 255) / 256;
    int nbE = (E + 255) / 256;
    int nbW = (M * 32 + 255) / 256;   // warp per node
    int gM  = (M + 127) / 128;        // 782

    // CSR build
    k_zero_deg<<<nbN, 256>>>(M);
    k_count<<<nbE, 256>>>(dst, E);
    k_scan1<<<nbN, 256>>>(M);
    k_scan2<<<1, 512>>>(nbN);
    k_scan3<<<nbN, 256>>>(M);
    k_fill<<<nbE, 256>>>(src, dst, E);

    // x -> planes + fp16 shadow
    k_cvt_x<<<(M * 16 + 255) / 256, 256>>>(x, M * 16);

    // ---- layer 1: 64 -> 128 ----
    k_prep_w<<<(128 * 128 + 255) / 256, 256>>>(Wl1, Wr1, 64, 128, 128);
    k_agg1h<<<nbW, 256>>>(pxf, M);
    k_gemm_cp<64, 64, 128><<<dim3(1, gM), 256, SM_TOT>>>(
        mh, ml, xh, xl, bl1, h1h, h1l, phf1, M);

    // ---- layer 2: 128 -> 128 ----
    k_prep_w<<<(128 * 256 + 255) / 256, 256>>>(Wl2, Wr2, 128, 256, 128);
    k_agg2h<<<nbW, 256>>>(phf1, M);
    k_gemm_cp<128, 128, 128><<<dim3(1, gM), 256, SM_TOT>>>(
        mh, ml, h1h, h1l, bl2, h2h, h2l, phf2, M);

    // ---- layer 3: 128 -> 256 ----
    k_prep_w<<<(256 * 256 + 255) / 256, 256>>>(Wl3, Wr3, 128, 256, 256);
    k_agg2h<<<nbW, 256>>>(phf2, M);
    k_gemm_cp<128, 128, 256><<<dim3(2, gM), 256, SM_TOT>>>(
        mh, ml, h2h, h2l, bl3, h3h, h3l, (__half*)nullptr, M);

    // ---- FC head: 256 -> 9 ----
    k_fc<<<(M + 7) / 8, 256>>>(h3h, h3l, Wfc, bfc, out, M);
}

// round 9
// speedup vs baseline: 1.0120x; 1.0023x over previous
#include <cuda_runtime.h>
#include <cuda_bf16.h>
#include <cuda_fp16.h>
#include <cstdint>

#define NNODES 100000
#define NEDGES 1600000

// ---------------- scratch (static __device__ — allocation-free) ----------------
__device__ int g_deg[NNODES], g_rowptr[NNODES], g_cursor[NNODES], g_col[NEDGES];
__device__ int g_bsum[512], g_boff[512];
// bf16 hi/lo planes (GEMM operands / outputs)
__device__ __nv_bfloat16 g_xh[NNODES * 64],   g_xl[NNODES * 64];
__device__ __nv_bfloat16 g_mh[NNODES * 128],  g_ml[NNODES * 128];
__device__ __nv_bfloat16 g_h1h[NNODES * 128], g_h1l[NNODES * 128];
__device__ __nv_bfloat16 g_h2h[NNODES * 128], g_h2l[NNODES * 128];
__device__ __nv_bfloat16 g_h3h[NNODES * 256], g_h3l[NNODES * 256];
__device__ __nv_bfloat16 g_wth[256 * 256],    g_wtl[256 * 256];
// fp16 shadows (agg gather path)
__device__ __half g_xf [NNODES * 64];
__device__ __half g_hf1[NNODES * 128];
__device__ __half g_hf2[NNODES * 128];

// ---------------- helpers ----------------
__device__ __forceinline__ uint32_t sw128(uint32_t b) { return b ^ ((b >> 3) & 0x70); }
__device__ __forceinline__ uint32_t cvta_smem(const void* p) {
    uint32_t a;
    asm("{ .reg .u64 t; cvta.to.shared.u64 t, %1; cvt.u32.u64 %0, t; }" : "=r"(a) : "l"(p));
    return a;
}
__device__ __forceinline__ void cpa16(uint32_t dst, const void* src, int sz) {
    asm volatile("cp.async.cg.shared.global [%0], [%1], 16, %2;"
                 :: "r"(dst), "l"(src), "r"(sz) : "memory");
}
__device__ __forceinline__ void ldsm4(uint32_t& r0, uint32_t& r1, uint32_t& r2, uint32_t& r3,
                                      uint32_t addr) {
    asm volatile("ldmatrix.sync.aligned.m8n8.x4.shared.b16 {%0,%1,%2,%3}, [%4];"
                 : "=r"(r0), "=r"(r1), "=r"(r2), "=r"(r3) : "r"(addr));
}
__device__ __forceinline__ void mma16816(float* c, const uint32_t* a, uint32_t b0, uint32_t b1) {
    asm volatile(
        "mma.sync.aligned.m16n8k16.row.col.f32.bf16.bf16.f32 "
        "{%0,%1,%2,%3}, {%4,%5,%6,%7}, {%8,%9}, {%0,%1,%2,%3};"
        : "+f"(c[0]), "+f"(c[1]), "+f"(c[2]), "+f"(c[3])
        : "r"(a[0]), "r"(a[1]), "r"(a[2]), "r"(a[3]), "r"(b0), "r"(b1));
}
__device__ __forceinline__ void split2(float v, __nv_bfloat16& h, __nv_bfloat16& l) {
    h = __float2bfloat16(v);
    l = __float2bfloat16(v - __bfloat162float(h));
}
__device__ __forceinline__ void split4(float4 v, uint2& H, uint2& L) {
    __nv_bfloat16 h0, l0, h1, l1, h2, l2, h3, l3;
    split2(v.x, h0, l0); split2(v.y, h1, l1);
    split2(v.z, h2, l2); split2(v.w, h3, l3);
    __nv_bfloat162 ph0 = __halves2bfloat162(h0, h1), ph1 = __halves2bfloat162(h2, h3);
    __nv_bfloat162 pl0 = __halves2bfloat162(l0, l1), pl1 = __halves2bfloat162(l2, l3);
    H = make_uint2(*(uint32_t*)&ph0, *(uint32_t*)&ph1);
    L = make_uint2(*(uint32_t*)&pl0, *(uint32_t*)&pl1);
}

// ---------------- CSR build ----------------
__global__ void k_zero_deg(int n) {
    int i = blockIdx.x * blockDim.x + threadIdx.x;
    if (i < n) g_deg[i] = 0;
}
__global__ void k_count(const int* __restrict__ dst, int E) {
    int e = blockIdx.x * blockDim.x + threadIdx.x;
    if (e < E) atomicAdd(&g_deg[dst[e]], 1);
}
__global__ void k_scan1(int n) {
    int tid = threadIdx.x, lane = tid & 31, warp = tid >> 5;
    int i = blockIdx.x * 256 + tid;
    int v = (i < n) ? g_deg[i] : 0;
    int x = v;
    #pragma unroll
    for (int o = 1; o < 32; o <<= 1) {
        int t = __shfl_up_sync(0xffffffffu, x, o);
        if (lane >= o) x += t;
    }
    __shared__ int wq[8];
    if (lane == 31) wq[warp] = x;
    __syncthreads();
    if (warp == 0) {
        int y = (lane < 8) ? wq[lane] : 0;
        int z = y;
        #pragma unroll
        for (int o = 1; o < 8; o <<= 1) {
            int t = __shfl_up_sync(0xffffffffu, z, o);
            if (lane >= o) z += t;
        }
        if (lane < 8) wq[lane] = z - y;
        if (lane == 7) g_bsum[blockIdx.x] = z;
    }
    __syncthreads();
    if (i < n) g_rowptr[i] = wq[warp] + x - v;
}
__global__ void k_scan2(int nb) {
    int tid = threadIdx.x, lane = tid & 31, warp = tid >> 5;
    int v = (tid < nb) ? g_bsum[tid] : 0;
    int x = v;
    #pragma unroll
    for (int o = 1; o < 32; o <<= 1) {
        int t = __shfl_up_sync(0xffffffffu, x, o);
        if (lane >= o) x += t;
    }
    __shared__ int wq[16];
    if (lane == 31) wq[warp] = x;
    __syncthreads();
    if (warp == 0) {
        int y = (lane < 16) ? wq[lane] : 0;
        int z = y;
        #pragma unroll
        for (int o = 1; o < 16; o <<= 1) {
            int t = __shfl_up_sync(0xffffffffu, z, o);
            if (lane >= o) z += t;
        }
        if (lane < 16) wq[lane] = z - y;
    }
    __syncthreads();
    if (tid < nb) g_boff[tid] = wq[warp] + x - v;
}
__global__ void k_scan3(int n) {
    int i = blockIdx.x * blockDim.x + threadIdx.x;
    if (i < n) {
        int r = g_rowptr[i] + g_boff[i >> 8];
        g_rowptr[i] = r;
        g_cursor[i] = r;
    }
}
__global__ void k_fill(const int* __restrict__ src, const int* __restrict__ dst, int E) {
    int e = blockIdx.x * blockDim.x + threadIdx.x;
    if (e < E) {
        int p = atomicAdd(&g_cursor[dst[e]], 1);
        g_col[p] = src[e];
    }
}

// ---------------- x -> fp16 shadow + bf16 planes ----------------
__global__ void k_cvt_x(const float* __restrict__ x, int n4) {
    int i = blockIdx.x * blockDim.x + threadIdx.x;
    if (i < n4) {
        float4 v = *(const float4*)(x + i * 4);
        uint2 H, L; split4(v, H, L);
        *(uint2*)(g_xh + i * 4) = H;
        *(uint2*)(g_xl + i * 4) = L;
        __half2 f0 = __floats2half2_rn(v.x, v.y), f1 = __floats2half2_rn(v.z, v.w);
        *(__half2*)(g_xf + i * 4)     = f0;
        *(__half2*)(g_xf + i * 4 + 2) = f1;
    }
}

// ---------------- weight prep: planes of Wt[n][k] = (k<K1 ? Wl[k][n] : Wr[k-K1][n]) ----------------
__global__ void k_prep_w(const float* __restrict__ Wl, const float* __restrict__ Wr,
                         int K1, int KT, int N) {
    int i = blockIdx.x * blockDim.x + threadIdx.x;
    if (i >= N * KT) return;
    int n = i / KT, k = i % KT;
    float v = (k < K1) ? Wl[k * N + n] : Wr[(k - K1) * N + n];
    __nv_bfloat16 h, l; split2(v, h, l);
    g_wth[n * KT + k] = h;
    g_wtl[n * KT + k] = l;
}

// ---------------- mean aggregation (fp16 gather, fp32 accum, bf16-plane output) ----------------
// D=64: lane owns 2 elems
__global__ void k_agg1h(const __half* __restrict__ xf, int n) {
    int gt = blockIdx.x * blockDim.x + threadIdx.x;
    int node = gt >> 5, lane = gt & 31;
    if (node >= n) return;
    float a0 = 0.f, a1 = 0.f;
    int s = g_rowptr[node], d = g_deg[node];
    int e = s, end = s + d;
    for (; e + 1 < end; e += 2) {
        float2 p0 = __half22float2(*(const __half2*)(xf + (size_t)g_col[e]     * 64 + 2 * lane));
        float2 p1 = __half22float2(*(const __half2*)(xf + (size_t)g_col[e + 1] * 64 + 2 * lane));
        a0 += p0.x + p1.x; a1 += p0.y + p1.y;
    }
    if (e < end) {
        float2 p0 = __half22float2(*(const __half2*)(xf + (size_t)g_col[e] * 64 + 2 * lane));
        a0 += p0.x; a1 += p0.y;
    }
    float inv = 1.0f / (float)(d > 0 ? d : 1);
    a0 *= inv; a1 *= inv;
    __nv_bfloat16 h0, l0, h1, l1;
    split2(a0, h0, l0); split2(a1, h1, l1);
    __nv_bfloat162 ph = __halves2bfloat162(h0, h1), pl = __halves2bfloat162(l0, l1);
    size_t o = (size_t)node * 64 + 2 * lane;
    *(uint32_t*)(g_mh + o) = *(uint32_t*)&ph;
    *(uint32_t*)(g_ml + o) = *(uint32_t*)&pl;
}
// D=128: lane owns 4 elems
__global__ void k_agg2h(const __half* __restrict__ hf, int n) {
    int gt = blockIdx.x * blockDim.x + threadIdx.x;
    int node = gt >> 5, lane = gt & 31;
    if (node >= n) return;
    float a0 = 0.f, a1 = 0.f, a2 = 0.f, a3 = 0.f;
    int s = g_rowptr[node], d = g_deg[node];
    int e = s, end = s + d;
    for (; e + 1 < end; e += 2) {
        uint2 u0 = *(const uint2*)(hf + (size_t)g_col[e]     * 128 + 4 * lane);
        uint2 u1 = *(const uint2*)(hf + (size_t)g_col[e + 1] * 128 + 4 * lane);
        float2 f0 = __half22float2(*(__half2*)&u0.x), f1 = __half22float2(*(__half2*)&u0.y);
        float2 f2 = __half22float2(*(__half2*)&u1.x), f3 = __half22float2(*(__half2*)&u1.y);
        a0 += f0.x + f2.x; a1 += f0.y + f2.y;
        a2 += f1.x + f3.x; a3 += f1.y + f3.y;
    }
    if (e < end) {
        uint2 u0 = *(const uint2*)(hf + (size_t)g_col[e] * 128 + 4 * lane);
        float2 f0 = __half22float2(*(__half2*)&u0.x), f1 = __half22float2(*(__half2*)&u0.y);
        a0 += f0.x; a1 += f0.y; a2 += f1.x; a3 += f1.y;
    }
    float inv = 1.0f / (float)(d > 0 ? d : 1);
    uint2 H, L;
    split4(make_float4(a0 * inv, a1 * inv, a2 * inv, a3 * inv), H, L);
    size_t o = (size_t)node * 128 + 4 * lane;
    *(uint2*)(g_mh + o) = H;
    *(uint2*)(g_ml + o) = L;
}

// ---------------- cp.async 2-stage HMMA GEMM (BK=64, 128KB smem, 1 CTA/SM) ----------------
// out planes = relu([A1|A2] @ Wt^T + bias); optional fp16 shadow for next agg.
// Stage layout (64KB): AH 0, AL 16K, WH 32K, WL 48K. Tiles 128 rows x 128B, sw128.
#define ST_SZ   65536
#define SM_TOT  131072

template <int K1, int K2, int NT>
__global__ void __launch_bounds__(256, 1) k_gemm_cp(
    const __nv_bfloat16* __restrict__ A1h, const __nv_bfloat16* __restrict__ A1l,
    const __nv_bfloat16* __restrict__ A2h, const __nv_bfloat16* __restrict__ A2l,
    const float* __restrict__ bias,
    __nv_bfloat16* __restrict__ Oh, __nv_bfloat16* __restrict__ Ol,
    __half* __restrict__ Of, int M)
{
    extern __shared__ char smem[];
    constexpr int KT = K1 + K2;
    constexpr int NC = KT / 64;
    uint32_t sb = cvta_smem(smem);
    int tid = threadIdx.x, lane = tid & 31, wid = tid >> 5;
    int wm = wid & 1, wn = wid >> 1;                       // 2m x 4n warp grid
    int bm = blockIdx.y * 128, bn = blockIdx.x * 128;

    float acc[4][4][4];
    #pragma unroll
    for (int mt = 0; mt < 4; mt++)
        #pragma unroll
        for (int nt = 0; nt < 4; nt++)
            #pragma unroll
            for (int j = 0; j < 4; j++) acc[mt][nt][j] = 0.f;

    // ldmatrix per-lane components (identical to R4/R6)
    int ar = lane & 15, ak = (lane >> 4) * 16;
    int nr = (lane & 7) + ((lane >> 4) << 3);
    int nk = ((lane >> 3) & 1) * 16;

    // this thread fills 4 chunks/plane: row = id>>3, cc = id&7
    int frow = tid >> 3, fcc = tid & 7;

    auto load_stage = [&](int st, int c) {
        const __nv_bfloat16 *Ah, *Al; int Ks, kb;
        if (c * 64 < K1) { Ah = A1h; Al = A1l; Ks = K1; kb = c * 64; }
        else             { Ah = A2h; Al = A2l; Ks = K2; kb = c * 64 - K1; }
        uint32_t base = sb + st * ST_SZ;
        #pragma unroll
        for (int q = 0; q < 4; q++) {
            int row = frow + q * 32;
            uint32_t so = base + sw128((uint32_t)(row * 128 + fcc * 16));
            int gr = bm + row;
            int sz = (gr < M) ? 16 : 0;
            int grc = (gr < M) ? gr : 0;
            const __nv_bfloat16* a_src = Ah + (size_t)grc * Ks + kb + fcc * 8;
            const __nv_bfloat16* l_src = Al + (size_t)grc * Ks + kb + fcc * 8;
            size_t wo = (size_t)(bn + row) * KT + c * 64 + fcc * 8;
            cpa16(so,         a_src, sz);
            cpa16(so + 16384, l_src, sz);
            cpa16(so + 32768, g_wth + wo, 16);
            cpa16(so + 49152, g_wtl + wo, 16);
        }
        asm volatile("cp.async.commit_group;" ::: "memory");
    };

    auto compute_stage = [&](int st) {
        uint32_t base = sb + st * ST_SZ;
        #pragma unroll
        for (int kk = 0; kk < 4; kk++) {
            uint32_t A_[4][4], W1[4][2], W2[4][2];
            uint32_t aoff[4], woff[2];
            #pragma unroll
            for (int mt = 0; mt < 4; mt++) {
                aoff[mt] = sw128((uint32_t)((wm * 64 + mt * 16 + ar) * 128 + ak + kk * 32));
                ldsm4(A_[mt][0], A_[mt][1], A_[mt][2], A_[mt][3], base + aoff[mt]);
            }
            #pragma unroll
            for (int h2 = 0; h2 < 2; h2++) {
                woff[h2] = sw128((uint32_t)((wn * 32 + h2 * 16 + nr) * 128 + nk + kk * 32));
                ldsm4(W1[h2 * 2][0], W1[h2 * 2][1], W1[h2 * 2 + 1][0], W1[h2 * 2 + 1][1],
                      base + 32768 + woff[h2]);
            }
            // hi(A) x hi(W)
            #pragma unroll
            for (int mt = 0; mt < 4; mt++)
                #pragma unroll
                for (int nt = 0; nt < 4; nt++)
                    mma16816(acc[mt][nt], A_[mt], W1[nt][0], W1[nt][1]);
            // hi(A) x lo(W)
            #pragma unroll
            for (int h2 = 0; h2 < 2; h2++)
                ldsm4(W2[h2 * 2][0], W2[h2 * 2][1], W2[h2 * 2 + 1][0], W2[h2 * 2 + 1][1],
                      base + 49152 + woff[h2]);
            #pragma unroll
            for (int mt = 0; mt < 4; mt++)
                #pragma unroll
                for (int nt = 0; nt < 4; nt++)
                    mma16816(acc[mt][nt], A_[mt], W2[nt][0], W2[nt][1]);
            // lo(A) x hi(W) — reuse A_ regs
            #pragma unroll
            for (int mt = 0; mt < 4; mt++)
                ldsm4(A_[mt][0], A_[mt][1], A_[mt][2], A_[mt][3], base + 16384 + aoff[mt]);
            #pragma unroll
            for (int mt = 0; mt < 4; mt++)
                #pragma unroll
                for (int nt = 0; nt < 4; nt++)
                    mma16816(acc[mt][nt], A_[mt], W1[nt][0], W1[nt][1]);
        }
    };

    load_stage(0, 0);
    for (int c = 0; c < NC; c++) {
        if (c + 1 < NC) {
            load_stage((c + 1) & 1, c + 1);
            asm volatile("cp.async.wait_group 1;" ::: "memory");
        } else {
            asm volatile("cp.async.wait_group 0;" ::: "memory");
        }
        __syncthreads();
        compute_stage(c & 1);
        __syncthreads();
    }

    // epilogue: bias + relu -> bf16 planes (+ fp16 shadow)
    int g = lane >> 2, t = lane & 3;
    #pragma unroll
    for (int nt = 0; nt < 4; nt++) {
        int col = bn + wn * 32 + nt * 8 + 2 * t;
        float2 bv = *(const float2*)(bias + col);
        #pragma unroll
        for (int mt = 0; mt < 4; mt++) {
            int r0 = bm + wm * 64 + mt * 16 + g;
            int r1 = r0 + 8;
            #pragma unroll
            for (int half_ = 0; half_ < 2; half_++) {
                int r = half_ ? r1 : r0;
                if (r >= M) continue;
                float f0 = fmaxf(acc[mt][nt][half_ * 2]     + bv.x, 0.f);
                float f1 = fmaxf(acc[mt][nt][half_ * 2 + 1] + bv.y, 0.f);
                __nv_bfloat16 h0, l0, h1, l1;
                split2(f0, h0, l0); split2(f1, h1, l1);
                __nv_bfloat162 ph = __halves2bfloat162(h0, h1);
                __nv_bfloat162 pl = __halves2bfloat162(l0, l1);
                *(uint32_t*)(Oh + (size_t)r * NT + col) = *(uint32_t*)&ph;
                *(uint32_t*)(Ol + (size_t)r * NT + col) = *(uint32_t*)&pl;
                if (Of) *(__half2*)(Of + (size_t)r * NT + col) = __floats2half2_rn(f0, f1);
            }
        }
    }
}

// ---------------- final FC: out = (hi+lo) @ Wfc + bfc  (256 -> 9), warp per node ----------------
__global__ void k_fc(const __nv_bfloat16* __restrict__ hh, const __nv_bfloat16* __restrict__ hl,
                     const float* __restrict__ W, const float* __restrict__ b,
                     float* __restrict__ out, int n) {
    __shared__ float sW[256 * 9];
    __shared__ float sb[9];
    for (int i = threadIdx.x; i < 256 * 9; i += blockDim.x) sW[i] = W[i];
    if (threadIdx.x < 9) sb[threadIdx.x] = b[threadIdx.x];
    __syncthreads();
    int warp = threadIdx.x >> 5, lane = threadIdx.x & 31;
    int node = blockIdx.x * 8 + warp;
    if (node >= n) return;
    float hv[8];
    #pragma unroll
    for (int r = 0; r < 8; r++) {
        size_t o = (size_t)node * 256 + r * 32 + lane;
        hv[r] = __bfloat162float(hh[o]) + __bfloat162float(hl[o]);
    }
    #pragma unroll
    for (int j = 0; j < 9; j++) {
        float s = 0.f;
        #pragma unroll
        for (int r = 0; r < 8; r++) s += hv[r] * sW[(r * 32 + lane) * 9 + j];
        #pragma unroll
        for (int o = 16; o > 0; o >>= 1) s += __shfl_xor_sync(0xffffffffu, s, o);
        if (lane == 0) out[node * 9 + j] = s + sb[j];
    }
}

// ---------------- launch ----------------
extern "C" void kernel_launch(void* const* d_in, const int* in_sizes, int n_in,
                              void* d_out, int out_size) {
    (void)n_in; (void)out_size;
    const float* x   = (const float*)d_in[0];
    const int*   ei  = (const int*)d_in[1];
    const float* Wl1 = (const float*)d_in[2];
    const float* bl1 = (const float*)d_in[3];
    const float* Wr1 = (const float*)d_in[4];
    const float* Wl2 = (const float*)d_in[5];
    const float* bl2 = (const float*)d_in[6];
    const float* Wr2 = (const float*)d_in[7];
    const float* Wl3 = (const float*)d_in[8];
    const float* bl3 = (const float*)d_in[9];
    const float* Wr3 = (const float*)d_in[10];
    const float* Wfc = (const float*)d_in[11];
    const float* bfc = (const float*)d_in[12];
    float* out = (float*)d_out;

    int M = in_sizes[0] / 64;
    int E = in_sizes[1] / 2;
    const int* src = ei;
    const int* dst = ei + E;

    __nv_bfloat16 *xh, *xl, *mh, *ml, *h1h, *h1l, *h2h, *h2l, *h3h, *h3l;
    __half *pxf, *phf1, *phf2;
    cudaGetSymbolAddress((void**)&xh,  g_xh);
    cudaGetSymbolAddress((void**)&xl,  g_xl);
    cudaGetSymbolAddress((void**)&mh,  g_mh);
    cudaGetSymbolAddress((void**)&ml,  g_ml);
    cudaGetSymbolAddress((void**)&h1h, g_h1h);
    cudaGetSymbolAddress((void**)&h1l, g_h1l);
    cudaGetSymbolAddress((void**)&h2h, g_h2h);
    cudaGetSymbolAddress((void**)&h2l, g_h2l);
    cudaGetSymbolAddress((void**)&h3h, g_h3h);
    cudaGetSymbolAddress((void**)&h3l, g_h3l);
    cudaGetSymbolAddress((void**)&pxf, g_xf);
    cudaGetSymbolAddress((void**)&phf1, g_hf1);
    cudaGetSymbolAddress((void**)&phf2, g_hf2);

    cudaFuncSetAttribute(k_gemm_cp<64, 64, 128>,
                         cudaFuncAttributeMaxDynamicSharedMemorySize, SM_TOT);
    cudaFuncSetAttribute(k_gemm_cp<128, 128, 128>,
                         cudaFuncAttributeMaxDynamicSharedMemorySize, SM_TOT);
    cudaFuncSetAttribute(k_gemm_cp<128, 128, 256>,
                         cudaFuncAttributeMaxDynamicSharedMemorySize, SM_TOT);

    int nbN = (M + 255) / 256;
    int nbE = (E + 255) / 256;
    int nbW = (M * 32 + 255) / 256;   // warp per node
    int gM  = (M + 127) / 128;        // 782

    // CSR build
    k_zero_deg<<<nbN, 256>>>(M);
    k_count<<<nbE, 256>>>(dst, E);
    k_scan1<<<nbN, 256>>>(M);
    k_scan2<<<1, 512>>>(nbN);
    k_scan3<<<nbN, 256>>>(M);
    k_fill<<<nbE, 256>>>(src, dst, E);

    // x -> planes + fp16 shadow
    k_cvt_x<<<(M * 16 + 255) / 256, 256>>>(x, M * 16);

    // ---- layer 1: 64 -> 128 ----
    k_prep_w<<<(128 * 128 + 255) / 256, 256>>>(Wl1, Wr1, 64, 128, 128);
    k_agg1h<<<nbW, 256>>>(pxf, M);
    k_gemm_cp<64, 64, 128><<<dim3(1, gM), 256, SM_TOT>>>(
        mh, ml, xh, xl, bl1, h1h, h1l, phf1, M);

    // ---- layer 2: 128 -> 128 ----
    k_prep_w<<<(128 * 256 + 255) / 256, 256>>>(Wl2, Wr2, 128, 256, 128);
    k_agg2h<<<nbW, 256>>>(phf1, M);
    k_gemm_cp<128, 128, 128><<<dim3(1, gM), 256, SM_TOT>>>(
        mh, ml, h1h, h1l, bl2, h2h, h2l, phf2, M);

    // ---- layer 3: 128 -> 256 ----
    k_prep_w<<<(256 * 256 + 255) / 256, 256>>>(Wl3, Wr3, 128, 256, 256);
    k_agg2h<<<nbW, 256>>>(phf2, M);
    k_gemm_cp<128, 128, 256><<<dim3(2, gM), 256, SM_TOT>>>(
        mh, ml, h2h, h2l, bl3, h3h, h3l, (__half*)nullptr, M);

    // ---- FC head: 256 -> 9 ----
    k_fc<<<(M + 7) / 8, 256>>>(h3h, h3l, Wfc, bfc, out, M);
}

// round 10
// speedup vs baseline: 1.1613x; 1.1474x over previous
#include <cuda_runtime.h>
#include <cuda_fp16.h>
#include <cstdint>

#define NNODES 100000
#define NEDGES 1600000

// ---------------- scratch (static __device__ — allocation-free) ----------------
__device__ int g_deg[NNODES], g_rowptr[NNODES], g_cursor[NNODES], g_col[NEDGES];
__device__ int g_bsum[512], g_boff[512];
// fp16 hi/lo planes: features (hi plane doubles as agg gather source)
__device__ __half g_xh[NNODES * 64],   g_xl[NNODES * 64];
__device__ __half g_mh[NNODES * 128],  g_ml[NNODES * 128];
__device__ __half g_h1h[NNODES * 128], g_h1l[NNODES * 128];
__device__ __half g_h2h[NNODES * 128], g_h2l[NNODES * 128];
__device__ __half g_h3h[NNODES * 256], g_h3l[NNODES * 256];
// single-plane fp16 weights, transposed-concat: w[n][k]
__device__ __half g_w1[128 * 128];
__device__ __half g_w2[128 * 256];
__device__ __half g_w3[256 * 256];

// ---------------- helpers ----------------
__device__ __forceinline__ uint32_t sw128(uint32_t b) { return b ^ ((b >> 3) & 0x70); }
__device__ __forceinline__ uint32_t cvta_smem(const void* p) {
    uint32_t a;
    asm("{ .reg .u64 t; cvta.to.shared.u64 t, %1; cvt.u32.u64 %0, t; }" : "=r"(a) : "l"(p));
    return a;
}
__device__ __forceinline__ void ldsm4(uint32_t& r0, uint32_t& r1, uint32_t& r2, uint32_t& r3,
                                      uint32_t addr) {
    asm volatile("ldmatrix.sync.aligned.m8n8.x4.shared.b16 {%0,%1,%2,%3}, [%4];"
                 : "=r"(r0), "=r"(r1), "=r"(r2), "=r"(r3) : "r"(addr));
}
__device__ __forceinline__ void mma16816h(float* c, const uint32_t* a, uint32_t b0, uint32_t b1) {
    asm volatile(
        "mma.sync.aligned.m16n8k16.row.col.f32.f16.f16.f32 "
        "{%0,%1,%2,%3}, {%4,%5,%6,%7}, {%8,%9}, {%0,%1,%2,%3};"
        : "+f"(c[0]), "+f"(c[1]), "+f"(c[2]), "+f"(c[3])
        : "r"(a[0]), "r"(a[1]), "r"(a[2]), "r"(a[3]), "r"(b0), "r"(b1));
}
__device__ __forceinline__ void hsplit(float v, __half& h, __half& l) {
    h = __float2half(v);
    l = __float2half(v - __half2float(h));
}

// ---------------- CSR build ----------------
__global__ void k_count(const int* __restrict__ dst, int E) {
    int e = blockIdx.x * blockDim.x + threadIdx.x;
    if (e < E) atomicAdd(&g_deg[dst[e]], 1);
}
__global__ void k_scan1(int n) {
    int tid = threadIdx.x, lane = tid & 31, warp = tid >> 5;
    int i = blockIdx.x * 256 + tid;
    int v = (i < n) ? g_deg[i] : 0;
    int x = v;
    #pragma unroll
    for (int o = 1; o < 32; o <<= 1) {
        int t = __shfl_up_sync(0xffffffffu, x, o);
        if (lane >= o) x += t;
    }
    __shared__ int wq[8];
    if (lane == 31) wq[warp] = x;
    __syncthreads();
    if (warp == 0) {
        int y = (lane < 8) ? wq[lane] : 0;
        int z = y;
        #pragma unroll
        for (int o = 1; o < 8; o <<= 1) {
            int t = __shfl_up_sync(0xffffffffu, z, o);
            if (lane >= o) z += t;
        }
        if (lane < 8) wq[lane] = z - y;
        if (lane == 7) g_bsum[blockIdx.x] = z;
    }
    __syncthreads();
    if (i < n) g_rowptr[i] = wq[warp] + x - v;
}
__global__ void k_scan2(int nb) {
    int tid = threadIdx.x, lane = tid & 31, warp = tid >> 5;
    int v = (tid < nb) ? g_bsum[tid] : 0;
    int x = v;
    #pragma unroll
    for (int o = 1; o < 32; o <<= 1) {
        int t = __shfl_up_sync(0xffffffffu, x, o);
        if (lane >= o) x += t;
    }
    __shared__ int wq[16];
    if (lane == 31) wq[warp] = x;
    __syncthreads();
    if (warp == 0) {
        int y = (lane < 16) ? wq[lane] : 0;
        int z = y;
        #pragma unroll
        for (int o = 1; o < 16; o <<= 1) {
            int t = __shfl_up_sync(0xffffffffu, z, o);
            if (lane >= o) z += t;
        }
        if (lane < 16) wq[lane] = z - y;
    }
    __syncthreads();
    if (tid < nb) g_boff[tid] = wq[warp] + x - v;
}
__global__ void k_scan3(int n) {
    int i = blockIdx.x * blockDim.x + threadIdx.x;
    if (i < n) {
        int r = g_rowptr[i] + g_boff[i >> 8];
        g_rowptr[i] = r;
        g_cursor[i] = r;
    }
}
__global__ void k_fill(const int* __restrict__ src, const int* __restrict__ dst, int E) {
    int e = blockIdx.x * blockDim.x + threadIdx.x;
    if (e < E) {
        int p = atomicAdd(&g_cursor[dst[e]], 1);
        g_col[p] = src[e];
    }
}

// ---------------- fused prologue: zero deg + split x + prep all weights (fp16) ----------------
__global__ void k_prologue(const float* __restrict__ x,
                           const float* __restrict__ Wl1, const float* __restrict__ Wr1,
                           const float* __restrict__ Wl2, const float* __restrict__ Wr2,
                           const float* __restrict__ Wl3, const float* __restrict__ Wr3,
                           int M) {
    int n0 = M;              // zero deg
    int n1 = M * 16;         // x in float4 groups
    int n2 = 128 * 128;      // W1
    int n3 = 128 * 256;      // W2
    int n4 = 256 * 256;      // W3
    int i = blockIdx.x * blockDim.x + threadIdx.x;
    if (i < n0) { g_deg[i] = 0; return; }
    i -= n0;
    if (i < n1) {
        float4 v = *(const float4*)(x + (size_t)i * 4);
        __half h0, l0, h1, l1, h2, l2, h3, l3;
        hsplit(v.x, h0, l0); hsplit(v.y, h1, l1);
        hsplit(v.z, h2, l2); hsplit(v.w, h3, l3);
        __half2 H0 = __halves2half2(h0, h1), H1 = __halves2half2(h2, h3);
        __half2 L0 = __halves2half2(l0, l1), L1 = __halves2half2(l2, l3);
        *(__half2*)(g_xh + (size_t)i * 4)     = H0;
        *(__half2*)(g_xh + (size_t)i * 4 + 2) = H1;
        *(__half2*)(g_xl + (size_t)i * 4)     = L0;
        *(__half2*)(g_xl + (size_t)i * 4 + 2) = L1;
        return;
    }
    i -= n1;
    if (i < n2) {   // W1: N=128, KT=128, K1=64
        int n = i / 128, k = i % 128;
        float v = (k < 64) ? Wl1[k * 128 + n] : Wr1[(k - 64) * 128 + n];
        g_w1[i] = __float2half(v);
        return;
    }
    i -= n2;
    if (i < n3) {   // W2: N=128, KT=256, K1=128
        int n = i / 256, k = i % 256;
        float v = (k < 128) ? Wl2[k * 128 + n] : Wr2[(k - 128) * 128 + n];
        g_w2[i] = __float2half(v);
        return;
    }
    i -= n3;
    if (i < n4) {   // W3: N=256, KT=256, K1=128
        int n = i / 256, k = i % 256;
        float v = (k < 128) ? Wl3[k * 256 + n] : Wr3[(k - 128) * 256 + n];
        g_w3[i] = __float2half(v);
    }
}

// ---------------- mean aggregation (fp16 hi-plane gather, fp32 accum, fp16-split out) ----------------
// D=64: lane owns 2 elems
__global__ void k_agg1(const __half* __restrict__ xf, int n) {
    int gt = blockIdx.x * blockDim.x + threadIdx.x;
    int node = gt >> 5, lane = gt & 31;
    if (node >= n) return;
    float a0 = 0.f, a1 = 0.f;
    int s = g_rowptr[node], d = g_deg[node];
    int e = s, end = s + d;
    for (; e + 1 < end; e += 2) {
        float2 p0 = __half22float2(*(const __half2*)(xf + (size_t)g_col[e]     * 64 + 2 * lane));
        float2 p1 = __half22float2(*(const __half2*)(xf + (size_t)g_col[e + 1] * 64 + 2 * lane));
        a0 += p0.x + p1.x; a1 += p0.y + p1.y;
    }
    if (e < end) {
        float2 p0 = __half22float2(*(const __half2*)(xf + (size_t)g_col[e] * 64 + 2 * lane));
        a0 += p0.x; a1 += p0.y;
    }
    float inv = 1.0f / (float)(d > 0 ? d : 1);
    a0 *= inv; a1 *= inv;
    __half h0, l0, h1, l1;
    hsplit(a0, h0, l0); hsplit(a1, h1, l1);
    size_t o = (size_t)node * 64 + 2 * lane;
    *(__half2*)(g_mh + o) = __halves2half2(h0, h1);
    *(__half2*)(g_ml + o) = __halves2half2(l0, l1);
}
// D=128: lane owns 4 elems
__global__ void k_agg2(const __half* __restrict__ hf, int n) {
    int gt = blockIdx.x * blockDim.x + threadIdx.x;
    int node = gt >> 5, lane = gt & 31;
    if (node >= n) return;
    float a0 = 0.f, a1 = 0.f, a2 = 0.f, a3 = 0.f;
    int s = g_rowptr[node], d = g_deg[node];
    int e = s, end = s + d;
    for (; e + 1 < end; e += 2) {
        uint2 u0 = *(const uint2*)(hf + (size_t)g_col[e]     * 128 + 4 * lane);
        uint2 u1 = *(const uint2*)(hf + (size_t)g_col[e + 1] * 128 + 4 * lane);
        float2 f0 = __half22float2(*(__half2*)&u0.x), f1 = __half22float2(*(__half2*)&u0.y);
        float2 f2 = __half22float2(*(__half2*)&u1.x), f3 = __half22float2(*(__half2*)&u1.y);
        a0 += f0.x + f2.x; a1 += f0.y + f2.y;
        a2 += f1.x + f3.x; a3 += f1.y + f3.y;
    }
    if (e < end) {
        uint2 u0 = *(const uint2*)(hf + (size_t)g_col[e] * 128 + 4 * lane);
        float2 f0 = __half22float2(*(__half2*)&u0.x), f1 = __half22float2(*(__half2*)&u0.y);
        a0 += f0.x; a1 += f0.y; a2 += f1.x; a3 += f1.y;
    }
    float inv = 1.0f / (float)(d > 0 ? d : 1);
    __half h0, l0, h1, l1, h2, l2, h3, l3;
    hsplit(a0 * inv, h0, l0); hsplit(a1 * inv, h1, l1);
    hsplit(a2 * inv, h2, l2); hsplit(a3 * inv, h3, l3);
    size_t o = (size_t)node * 128 + 4 * lane;
    *(__half2*)(g_mh + o)     = __halves2half2(h0, h1);
    *(__half2*)(g_mh + o + 2) = __halves2half2(h2, h3);
    *(__half2*)(g_ml + o)     = __halves2half2(l0, l1);
    *(__half2*)(g_ml + o + 2) = __halves2half2(l2, l3);
}

// ---------------- HMMA fp16 2-term GEMM: out = relu([A1|A2] @ W^T + bias) ----------------
// A planes fp16 (hi/lo), W single fp16 plane [NT,KT]; outputs fp16 hi/lo planes.
// CTA 128x128, 8 warps (2m x 4n), K-chunk 64. Sync fill, 48KB smem, 2 CTAs/SM.
#define SM_AH 0
#define SM_AL 16384
#define SM_W  32768
#define SM_TOT 49152

template <int K1, int K2, int NT>
__global__ void __launch_bounds__(256, 2) k_gemm(
    const __half* __restrict__ A1h, const __half* __restrict__ A1l,
    const __half* __restrict__ A2h, const __half* __restrict__ A2l,
    const __half* __restrict__ W,  const float* __restrict__ bias,
    __half* __restrict__ Oh, __half* __restrict__ Ol, int M)
{
    extern __shared__ char smem[];
    constexpr int KT = K1 + K2;
    constexpr int NC = KT / 64;
    uint32_t sb = cvta_smem(smem);
    int tid = threadIdx.x, lane = tid & 31, wid = tid >> 5;
    int wm = wid & 1, wn = wid >> 1;           // 2m x 4n warp grid
    int bm = blockIdx.y * 128, bn = blockIdx.x * 128;

    float acc[4][4][4];
    #pragma unroll
    for (int mt = 0; mt < 4; mt++)
        #pragma unroll
        for (int nt = 0; nt < 4; nt++)
            #pragma unroll
            for (int j = 0; j < 4; j++) acc[mt][nt][j] = 0.f;

    // ldmatrix per-lane components (x4, non-trans) — proven mapping
    int ar = lane & 15, ak = (lane >> 4) * 16;
    int nr = (lane & 7) + ((lane >> 4) << 3);
    int nk = ((lane >> 3) & 1) * 16;

    int frow = tid >> 3, fcc = tid & 7;        // fill: row, 16B-chunk (8 per 128B row)

    for (int c = 0; c < NC; c++) {
        const __half *Ah, *Al; int Ks, kb;
        if (c * 64 < K1) { Ah = A1h; Al = A1l; Ks = K1; kb = c * 64; }
        else             { Ah = A2h; Al = A2l; Ks = K2; kb = c * 64 - K1; }

        // fill 3 tiles (AH, AL, W), each 128 rows x 64 fp16 (128B rows), sw128
        #pragma unroll
        for (int q = 0; q < 4; q++) {
            int row = frow + q * 32;
            uint32_t so = sw128((uint32_t)(row * 128 + fcc * 16));
            int gr = bm + row;
            uint4 vh = make_uint4(0, 0, 0, 0), vl = make_uint4(0, 0, 0, 0);
            if (gr < M) {
                vh = *(const uint4*)(Ah + (size_t)gr * Ks + kb + fcc * 8);
                vl = *(const uint4*)(Al + (size_t)gr * Ks + kb + fcc * 8);
            }
            *(uint4*)(smem + SM_AH + so) = vh;
            *(uint4*)(smem + SM_AL + so) = vl;
            *(uint4*)(smem + SM_W + so) =
                *(const uint4*)(W + (size_t)(bn + row) * KT + c * 64 + fcc * 8);
        }
        __syncthreads();

        #pragma unroll
        for (int kk = 0; kk < 4; kk++) {
            uint32_t A_[4][4], Wf[4][2];
            uint32_t aoff[4];
            #pragma unroll
            for (int mt = 0; mt < 4; mt++) {
                aoff[mt] = sw128((uint32_t)((wm * 64 + mt * 16 + ar) * 128 + ak + kk * 32));
                ldsm4(A_[mt][0], A_[mt][1], A_[mt][2], A_[mt][3], sb + SM_AH + aoff[mt]);
            }
            #pragma unroll
            for (int h2 = 0; h2 < 2; h2++) {
                uint32_t woff = sw128((uint32_t)((wn * 32 + h2 * 16 + nr) * 128 + nk + kk * 32));
                ldsm4(Wf[h2 * 2][0], Wf[h2 * 2][1], Wf[h2 * 2 + 1][0], Wf[h2 * 2 + 1][1],
                      sb + SM_W + woff);
            }
            // hi(A) x W
            #pragma unroll
            for (int mt = 0; mt < 4; mt++)
                #pragma unroll
                for (int nt = 0; nt < 4; nt++)
                    mma16816h(acc[mt][nt], A_[mt], Wf[nt][0], Wf[nt][1]);
            // lo(A) x W — reuse A_ regs
            #pragma unroll
            for (int mt = 0; mt < 4; mt++)
                ldsm4(A_[mt][0], A_[mt][1], A_[mt][2], A_[mt][3], sb + SM_AL + aoff[mt]);
            #pragma unroll
            for (int mt = 0; mt < 4; mt++)
                #pragma unroll
                for (int nt = 0; nt < 4; nt++)
                    mma16816h(acc[mt][nt], A_[mt], Wf[nt][0], Wf[nt][1]);
        }
        __syncthreads();
    }

    // epilogue: bias + relu -> fp16 hi/lo planes
    int g = lane >> 2, t = lane & 3;
    #pragma unroll
    for (int nt = 0; nt < 4; nt++) {
        int col = bn + wn * 32 + nt * 8 + 2 * t;
        float2 bv = *(const float2*)(bias + col);
        #pragma unroll
        for (int mt = 0; mt < 4; mt++) {
            #pragma unroll
            for (int half_ = 0; half_ < 2; half_++) {
                int r = bm + wm * 64 + mt * 16 + g + half_ * 8;
                if (r >= M) continue;
                float f0 = fmaxf(acc[mt][nt][half_ * 2]     + bv.x, 0.f);
                float f1 = fmaxf(acc[mt][nt][half_ * 2 + 1] + bv.y, 0.f);
                __half h0, l0, h1, l1;
                hsplit(f0, h0, l0); hsplit(f1, h1, l1);
                *(__half2*)(Oh + (size_t)r * NT + col) = __halves2half2(h0, h1);
                *(__half2*)(Ol + (size_t)r * NT + col) = __halves2half2(l0, l1);
            }
        }
    }
}

// ---------------- final FC: out = (hi+lo) @ Wfc + bfc  (256 -> 9), warp per node ----------------
__global__ void k_fc(const __half* __restrict__ hh, const __half* __restrict__ hl,
                     const float* __restrict__ W, const float* __restrict__ b,
                     float* __restrict__ out, int n) {
    __shared__ float sW[256 * 9];
    __shared__ float sb[9];
    for (int i = threadIdx.x; i < 256 * 9; i += blockDim.x) sW[i] = W[i];
    if (threadIdx.x < 9) sb[threadIdx.x] = b[threadIdx.x];
    __syncthreads();
    int warp = threadIdx.x >> 5, lane = threadIdx.x & 31;
    int node = blockIdx.x * 8 + warp;
    if (node >= n) return;
    float hv[8];
    #pragma unroll
    for (int r = 0; r < 8; r++) {
        size_t o = (size_t)node * 256 + r * 32 + lane;
        hv[r] = __half2float(hh[o]) + __half2float(hl[o]);
    }
    #pragma unroll
    for (int j = 0; j < 9; j++) {
        float s = 0.f;
        #pragma unroll
        for (int r = 0; r < 8; r++) s += hv[r] * sW[(r * 32 + lane) * 9 + j];
        #pragma unroll
        for (int o = 16; o > 0; o >>= 1) s += __shfl_xor_sync(0xffffffffu, s, o);
        if (lane == 0) out[node * 9 + j] = s + sb[j];
    }
}

// ---------------- launch ----------------
extern "C" void kernel_launch(void* const* d_in, const int* in_sizes, int n_in,
                              void* d_out, int out_size) {
    (void)n_in; (void)out_size;
    const float* x   = (const float*)d_in[0];
    const int*   ei  = (const int*)d_in[1];
    const float* Wl1 = (const float*)d_in[2];
    const float* bl1 = (const float*)d_in[3];
    const float* Wr1 = (const float*)d_in[4];
    const float* Wl2 = (const float*)d_in[5];
    const float* bl2 = (const float*)d_in[6];
    const float* Wr2 = (const float*)d_in[7];
    const float* Wl3 = (const float*)d_in[8];
    const float* bl3 = (const float*)d_in[9];
    const float* Wr3 = (const float*)d_in[10];
    const float* Wfc = (const float*)d_in[11];
    const float* bfc = (const float*)d_in[12];
    float* out = (float*)d_out;

    int M = in_sizes[0] / 64;
    int E = in_sizes[1] / 2;
    const int* src = ei;
    const int* dst = ei + E;

    __half *xh, *xl, *mh, *ml, *h1h, *h1l, *h2h, *h2l, *h3h, *h3l, *w1, *w2, *w3;
    cudaGetSymbolAddress((void**)&xh,  g_xh);
    cudaGetSymbolAddress((void**)&xl,  g_xl);
    cudaGetSymbolAddress((void**)&mh,  g_mh);
    cudaGetSymbolAddress((void**)&ml,  g_ml);
    cudaGetSymbolAddress((void**)&h1h, g_h1h);
    cudaGetSymbolAddress((void**)&h1l, g_h1l);
    cudaGetSymbolAddress((void**)&h2h, g_h2h);
    cudaGetSymbolAddress((void**)&h2l, g_h2l);
    cudaGetSymbolAddress((void**)&h3h, g_h3h);
    cudaGetSymbolAddress((void**)&h3l, g_h3l);
    cudaGetSymbolAddress((void**)&w1,  g_w1);
    cudaGetSymbolAddress((void**)&w2,  g_w2);
    cudaGetSymbolAddress((void**)&w3,  g_w3);

    cudaFuncSetAttribute(k_gemm<64, 64, 128>,
                         cudaFuncAttributeMaxDynamicSharedMemorySize, SM_TOT);
    cudaFuncSetAttribute(k_gemm<128, 128, 128>,
                         cudaFuncAttributeMaxDynamicSharedMemorySize, SM_TOT);
    cudaFuncSetAttribute(k_gemm<128, 128, 256>,
                         cudaFuncAttributeMaxDynamicSharedMemorySize, SM_TOT);

    int nbN = (M + 255) / 256;
    int nbE = (E + 255) / 256;
    int nbW = (M * 32 + 255) / 256;   // warp per node
    int gM  = (M + 127) / 128;        // 782

    // prologue: zero deg + split x + prep all weights
    int prologue_items = M + M * 16 + 128 * 128 + 128 * 256 + 256 * 256;
    k_prologue<<<(prologue_items + 255) / 256, 256>>>(x, Wl1, Wr1, Wl2, Wr2, Wl3, Wr3, M);

    // CSR build
    k_count<<<nbE, 256>>>(dst, E);
    k_scan1<<<nbN, 256>>>(M);
    k_scan2<<<1, 512>>>(nbN);
    k_scan3<<<nbN, 256>>>(M);
    k_fill<<<nbE, 256>>>(src, dst, E);

    // ---- layer 1: 64 -> 128 ----
    k_agg1<<<nbW, 256>>>(xh, M);
    k_gemm<64, 64, 128><<<dim3(1, gM), 256, SM_TOT>>>(
        mh, ml, xh, xl, w1, bl1, h1h, h1l, M);

    // ---- layer 2: 128 -> 128 ----
    k_agg2<<<nbW, 256>>>(h1h, M);
    k_gemm<128, 128, 128><<<dim3(1, gM), 256, SM_TOT>>>(
        mh, ml, h1h, h1l, w2, bl2, h2h, h2l, M);

    // ---- layer 3: 128 -> 256 ----
    k_agg2<<<nbW, 256>>>(h2h, M);
    k_gemm<128, 128, 256><<<dim3(2, gM), 256, SM_TOT>>>(
        mh, ml, h2h, h2l, w3, bl3, h3h, h3l, M);

    // ---- FC head: 256 -> 9 ----
    k_fc<<<(M + 7) / 8, 256>>>(h3h, h3l, Wfc, bfc, out, M);
}